// round 14
// baseline (speedup 1.0000x reference)
#include <cuda_runtime.h>
#include <cuda_fp16.h>
#include <cstdint>

#define BDIM 2
#define TSEQ 2048
#define NH 16
#define HD 64
#define DM 1024
#define MTOT (BDIM*TSEQ)

// ---------------- scratch (allocation-free: __device__ globals) ----------------
__device__ uint4 g_xh[(size_t)MTOT*DM*2/16];
__device__ uint4 g_w1h[(size_t)3*DM*DM*2/16];
__device__ uint4 g_w2h[(size_t)DM*DM*2/16];
__device__ uint4 g_qh[(size_t)BDIM*NH*TSEQ*HD*2/16];
__device__ uint4 g_kh[(size_t)BDIM*NH*TSEQ*HD*2/16];
__device__ uint4 g_vh[(size_t)BDIM*NH*TSEQ*HD*2/16];
__device__ uint4 g_ah[(size_t)MTOT*DM*2/16];

// ---------------- helpers ----------------
__device__ __forceinline__ uint32_t smem_u32(const void* p) {
    uint32_t a;
    asm("{ .reg .u64 t; cvta.to.shared.u64 t, %1; cvt.u32.u64 %0, t; }" : "=r"(a) : "l"(p));
    return a;
}
__device__ __forceinline__ void cpasync16(uint32_t dst, const void* src) {
    asm volatile("cp.async.cg.shared.global [%0], [%1], 16;" :: "r"(dst), "l"(src) : "memory");
}
#define CP_COMMIT() asm volatile("cp.async.commit_group;" ::: "memory")
#define CP_WAIT1()  asm volatile("cp.async.wait_group 1;" ::: "memory")
#define CP_WAIT0()  asm volatile("cp.async.wait_group 0;" ::: "memory")
__device__ __forceinline__ void ldsm4(uint32_t* r, uint32_t addr) {
    asm volatile("ldmatrix.sync.aligned.m8n8.x4.shared.b16 {%0,%1,%2,%3}, [%4];"
        : "=r"(r[0]), "=r"(r[1]), "=r"(r[2]), "=r"(r[3]) : "r"(addr));
}
__device__ __forceinline__ void ldsm4t(uint32_t* r, uint32_t addr) {
    asm volatile("ldmatrix.sync.aligned.m8n8.x4.trans.shared.b16 {%0,%1,%2,%3}, [%4];"
        : "=r"(r[0]), "=r"(r[1]), "=r"(r[2]), "=r"(r[3]) : "r"(addr));
}
__device__ __forceinline__ void mma_f16(float* c, const uint32_t* a, const uint32_t* b) {
    asm volatile(
        "mma.sync.aligned.m16n8k16.row.col.f32.f16.f16.f32 "
        "{%0,%1,%2,%3}, {%4,%5,%6,%7}, {%8,%9}, {%0,%1,%2,%3};"
        : "+f"(c[0]), "+f"(c[1]), "+f"(c[2]), "+f"(c[3])
        : "r"(a[0]), "r"(a[1]), "r"(a[2]), "r"(a[3]), "r"(b[0]), "r"(b[1]));
}
__device__ __forceinline__ uint32_t pack_h2(float a, float b) {
    __half2 h = __floats2half2_rn(a, b);
    return reinterpret_cast<uint32_t&>(h);
}

// ---------------- fused fp32 -> fp16 convert over 3 tensors ----------------
#define SPLIT_N0 (MTOT*DM/4)
#define SPLIT_N1 (3*DM*DM/4)
#define SPLIT_N2 (DM*DM/4)
#define SPLIT_TOT (SPLIT_N0 + SPLIT_N1 + SPLIT_N2)

__global__ __launch_bounds__(256)
void cvt3_kernel(const float* __restrict__ s0, const float* __restrict__ s1,
                 const float* __restrict__ s2)
{
    int i = blockIdx.x * blockDim.x + threadIdx.x;
    if (i >= SPLIT_TOT) return;
    const float* s; __half* hi; int j;
    if (i < SPLIT_N0)                  { s = s0; hi = (__half*)g_xh;  j = i; }
    else if (i < SPLIT_N0 + SPLIT_N1)  { s = s1; hi = (__half*)g_w1h; j = i - SPLIT_N0; }
    else                               { s = s2; hi = (__half*)g_w2h; j = i - SPLIT_N0 - SPLIT_N1; }
    float4 v = ((const float4*)s)[j];
    ((uint2*)hi)[j] = make_uint2(pack_h2(v.x, v.y), pack_h2(v.z, v.w));
}

// ---------------- persistent mma.sync GEMM, BK=64, 3-stage, 1 barrier/chunk -----
#define BK 64
#define NCH (DM / BK)               // 16
#define TILE_B 16384                // 128 rows x 128B
#define STAGE_B (2 * TILE_B)        // A, W: 32768
#define GEMM_SMEM (3 * STAGE_B)     // 98304

template<bool SCATTER>
__global__ __launch_bounds__(256, 2)
void mma_gemm(const __half* __restrict__ A, const __half* __restrict__ W,
              const float* __restrict__ bias, float* __restrict__ C, int N)
{
    extern __shared__ char smem[];
    const uint32_t sbase = smem_u32(smem);
    const int tid = threadIdx.x, wid = tid >> 5, lane = tid & 31;
    const int wm = wid & 3, wn = wid >> 2;
    const int K = DM;
    const int nx = N >> 7;
    const int ntile = (MTOT >> 7) * nx;
    const int ntile_own = (ntile - (int)blockIdx.x + (int)gridDim.x - 1) / (int)gridDim.x;
    const int F = ntile_own * NCH;       // flat chunk count for this CTA

    // flat chunk ff -> (tile, k-chunk); stage = ff % 3
    auto load_flat = [&](int ff) {
        const int tl = ff >> 4;          // NCH = 16
        const int tile = (int)blockIdx.x + tl * (int)gridDim.x;
        const int c = ff & 15;
        const int m0 = (tile / nx) << 7, n0 = (tile % nx) << 7;
        const uint32_t st = sbase + (uint32_t)(ff % 3) * STAGE_B;
        const int k0 = c * BK;
        #pragma unroll
        for (int t = 0; t < 4; t++) {
            int idx = tid + t * 256;
            int row = idx >> 3, ch = idx & 7;
            uint32_t so = (uint32_t)(row * 128 + ((ch ^ (row & 7)) * 16));
            int gk = k0 + ch * 8;
            cpasync16(st + so,          A + (size_t)(m0 + row) * K + gk);
            cpasync16(st + TILE_B + so, W + (size_t)(n0 + row) * K + gk);
        }
        CP_COMMIT();
    };

    const int arowoff = lane & 15;
    const int akoff   = lane >> 4;
    const int browoff = (lane & 7) + ((lane >> 4) << 3);
    const int bkoff   = (lane >> 3) & 1;

    int rowA[2];
    #pragma unroll
    for (int mt = 0; mt < 2; mt++)
        rowA[mt] = wm * 32 + mt * 16 + arowoff;
    int rowB[4];
    #pragma unroll
    for (int nt2 = 0; nt2 < 4; nt2++)
        rowB[nt2] = wn * 64 + nt2 * 16 + browoff;

    if (F > 0) load_flat(0);
    if (F > 1) load_flat(1);

    int f = 0;
    for (int tile = blockIdx.x; tile < ntile; tile += gridDim.x) {
        const int m0 = (tile / nx) << 7, n0 = (tile % nx) << 7;

        float acc[2][8][4];
        #pragma unroll
        for (int mt = 0; mt < 2; mt++)
            #pragma unroll
            for (int nt = 0; nt < 8; nt++)
                #pragma unroll
                for (int q = 0; q < 4; q++) acc[mt][nt][q] = 0.f;

        for (int c = 0; c < NCH; c++, f++) {
            if (f + 1 < F) { CP_WAIT1(); } else { CP_WAIT0(); }
            __syncthreads();                      // single barrier per chunk
            if (f + 2 < F) load_flat(f + 2);

            const uint32_t st = sbase + (uint32_t)(f % 3) * STAGE_B;
            #pragma unroll
            for (int s = 0; s < 4; s++) {
                uint32_t ah[2][4];
                #pragma unroll
                for (int mt = 0; mt < 2; mt++) {
                    uint32_t off = (uint32_t)(rowA[mt] * 128 + (((2*s + akoff) ^ (rowA[mt] & 7)) * 16));
                    ldsm4(ah[mt], st + off);
                }
                uint32_t bh[4][4];
                #pragma unroll
                for (int nt2 = 0; nt2 < 4; nt2++) {
                    uint32_t off = (uint32_t)(rowB[nt2] * 128 + (((2*s + bkoff) ^ (rowB[nt2] & 7)) * 16));
                    ldsm4(bh[nt2], st + TILE_B + off);
                }
                #pragma unroll
                for (int mt = 0; mt < 2; mt++)
                    #pragma unroll
                    for (int nt = 0; nt < 8; nt++)
                        mma_f16(acc[mt][nt], ah[mt], &bh[nt >> 1][(nt & 1) * 2]);
            }
        }

        const int lr = lane >> 2, lc = (lane & 3) * 2;
        #pragma unroll
        for (int mt = 0; mt < 2; mt++) {
            #pragma unroll
            for (int half = 0; half < 2; half++) {
                const int m = m0 + wm * 32 + mt * 16 + lr + half * 8;
                #pragma unroll
                for (int nt = 0; nt < 8; nt++) {
                    const int n = n0 + wn * 64 + nt * 8 + lc;
                    float rx = acc[mt][nt][half * 2 + 0] + bias[n + 0];
                    float ry = acc[mt][nt][half * 2 + 1] + bias[n + 1];
                    if (!SCATTER) {
                        *(float2*)&C[(size_t)m * N + n] = make_float2(rx, ry);
                    } else {
                        int mat = n >> 10, h = (n >> 6) & 15, d = n & 63;
                        int b = m >> 11, t = m & 2047;
                        // q pre-scaled by 0.125 * log2(e) so flash can use exp2
                        if (mat == 0) { rx *= 0.18033688f; ry *= 0.18033688f; }
                        __half* dh = (mat == 0) ? (__half*)g_qh
                                    : (mat == 1) ? (__half*)g_kh : (__half*)g_vh;
                        size_t off = (((size_t)(b * NH + h) * TSEQ) + t) * HD + d;
                        *(uint32_t*)&dh[off] = pack_h2(rx, ry);
                    }
                }
            }
        }
    }
}

// ---------------- flash attention: 2 key-tiles per stage, 1 barrier per pair ----
#define FL_Q 0u
#define FL_STG 16384u
#define FL_SSZ 32768u              // [K0 8K | V0 8K | K1 8K | V1 8K]
#define FL_SMEM (FL_STG + 2 * FL_SSZ)   // 81920

__global__ __launch_bounds__(256, 2)
void flash_mma(const __half* __restrict__ qh_g,
               const __half* __restrict__ kh_g, const __half* __restrict__ vh_g,
               __half* __restrict__ oh_g)
{
    extern __shared__ char smem[];
    const uint32_t sb = smem_u32(smem);
    const int tid = threadIdx.x, wid = tid >> 5, lane = tid & 31;
    const int bh = blockIdx.y;
    const int qb = gridDim.x - 1 - blockIdx.x;     // heavy tiles first
    const int qbase = qb * 128;
    const size_t base = (size_t)bh * TSEQ * HD;
    const int npair = qb + 1;                      // (2qb+2)/2 key-tile pairs

    auto ldq = [&]() {
        #pragma unroll
        for (int t = 0; t < 4; t++) {
            int idx = tid + t * 256;
            int row = idx >> 3, ch = idx & 7;
            uint32_t so = (uint32_t)(row * 128 + ((ch ^ (row & 7)) * 16));
            cpasync16(sb + FL_Q + so, qh_g + base + (size_t)(qbase + row) * HD + ch * 8);
        }
    };
    // load key-tile pair p (tiles 2p, 2p+1) into stage p%2
    auto ldkv2 = [&](int p) {
        const uint32_t st = sb + FL_STG + (uint32_t)(p & 1) * FL_SSZ;
        #pragma unroll
        for (int t = 0; t < 4; t++) {
            int idx = tid + t * 256;               // 0..1023: 128 rows x 8 chunks
            int row = idx >> 3, ch = idx & 7;
            int sub = row >> 6, lrow = row & 63;
            uint32_t so = (uint32_t)(lrow * 128 + ((ch ^ (lrow & 7)) * 16));
            size_t g = base + (size_t)((2*p + sub) * 64 + lrow) * HD + ch * 8;
            cpasync16(st + (uint32_t)sub * 16384 + so,        kh_g + g);
            cpasync16(st + (uint32_t)sub * 16384 + 8192 + so, vh_g + g);
        }
        CP_COMMIT();
    };

    ldq();
    ldkv2(0);

    const int arow = wid * 16 + (lane & 15);
    const int akoff = lane >> 4;
    const int brow_off = (lane & 7) + ((lane >> 4) << 3);
    const int bkoff = (lane >> 3) & 1;
    const int vrow_off = (lane & 7) + (((lane >> 3) & 1) << 3);
    const int vcg = lane >> 4;

    const int wrow0 = qbase + wid * 16;
    const int wrow_max = wrow0 + 15;

    uint32_t qh[4][4];
    float acc_o[8][4];
    #pragma unroll
    for (int nt = 0; nt < 8; nt++)
        #pragma unroll
        for (int q = 0; q < 4; q++) acc_o[nt][q] = 0.f;
    float m0 = -1e30f, m1 = -1e30f, l0 = 0.f, l1 = 0.f;

    const int r0g = wrow0 + (lane >> 2);
    const int r1g = r0g + 8;

    for (int p = 0; p < npair; p++) {
        CP_WAIT0();
        __syncthreads();                           // single barrier per pair
        if (p + 1 < npair) ldkv2(p + 1);

        if (p == 0) {
            #pragma unroll
            for (int s4 = 0; s4 < 4; s4++) {
                uint32_t off = (uint32_t)(arow * 128 + (((2*s4 + akoff) ^ (arow & 7)) * 16));
                ldsm4(qh[s4], sb + FL_Q + off);
            }
        }

        const uint32_t stp = sb + FL_STG + (uint32_t)(p & 1) * FL_SSZ;

        #pragma unroll
        for (int sub = 0; sub < 2; sub++) {
            const int kbase = (2*p + sub) * 64;
            if (kbase > wrow_max) continue;        // fully-masked: exact zero contribution
            const uint32_t st = stp + (uint32_t)sub * 16384;

            float s[8][4];
            #pragma unroll
            for (int nt = 0; nt < 8; nt++)
                #pragma unroll
                for (int q = 0; q < 4; q++) s[nt][q] = 0.f;

            #pragma unroll
            for (int s4 = 0; s4 < 4; s4++) {
                uint32_t kh[4][4];
                #pragma unroll
                for (int nt2 = 0; nt2 < 4; nt2++) {
                    int row = nt2 * 16 + brow_off;
                    uint32_t off = (uint32_t)(row * 128 + (((2*s4 + bkoff) ^ (row & 7)) * 16));
                    ldsm4(kh[nt2], st + off);
                }
                #pragma unroll
                for (int nt = 0; nt < 8; nt++)
                    mma_f16(s[nt], qh[s4], &kh[nt >> 1][(nt & 1) * 2]);
            }

            if (kbase + 63 > wrow0) {
                #pragma unroll
                for (int nt = 0; nt < 8; nt++) {
                    int kg0 = kbase + nt * 8 + 2 * (lane & 3);
                    if (kg0 > r0g)     s[nt][0] = -1e30f;
                    if (kg0 + 1 > r0g) s[nt][1] = -1e30f;
                    if (kg0 > r1g)     s[nt][2] = -1e30f;
                    if (kg0 + 1 > r1g) s[nt][3] = -1e30f;
                }
            }

            float mx0 = -1e30f, mx1 = -1e30f;
            #pragma unroll
            for (int nt = 0; nt < 8; nt++) {
                mx0 = fmaxf(mx0, fmaxf(s[nt][0], s[nt][1]));
                mx1 = fmaxf(mx1, fmaxf(s[nt][2], s[nt][3]));
            }
            mx0 = fmaxf(mx0, __shfl_xor_sync(0xffffffffu, mx0, 1));
            mx0 = fmaxf(mx0, __shfl_xor_sync(0xffffffffu, mx0, 2));
            mx1 = fmaxf(mx1, __shfl_xor_sync(0xffffffffu, mx1, 1));
            mx1 = fmaxf(mx1, __shfl_xor_sync(0xffffffffu, mx1, 2));
            float mn0 = fmaxf(m0, mx0), mn1 = fmaxf(m1, mx1);
            float a0 = exp2f(m0 - mn0), a1 = exp2f(m1 - mn1);
            float sum0 = 0.f, sum1 = 0.f;
            #pragma unroll
            for (int nt = 0; nt < 8; nt++) {
                s[nt][0] = exp2f(s[nt][0] - mn0);
                s[nt][1] = exp2f(s[nt][1] - mn0);
                s[nt][2] = exp2f(s[nt][2] - mn1);
                s[nt][3] = exp2f(s[nt][3] - mn1);
                sum0 += s[nt][0] + s[nt][1];
                sum1 += s[nt][2] + s[nt][3];
            }
            sum0 += __shfl_xor_sync(0xffffffffu, sum0, 1);
            sum0 += __shfl_xor_sync(0xffffffffu, sum0, 2);
            sum1 += __shfl_xor_sync(0xffffffffu, sum1, 1);
            sum1 += __shfl_xor_sync(0xffffffffu, sum1, 2);
            l0 = l0 * a0 + sum0; m0 = mn0;
            l1 = l1 * a1 + sum1; m1 = mn1;
            #pragma unroll
            for (int nt = 0; nt < 8; nt++) {
                acc_o[nt][0] *= a0; acc_o[nt][1] *= a0;
                acc_o[nt][2] *= a1; acc_o[nt][3] *= a1;
            }

            uint32_t phi[4][4];
            #pragma unroll
            for (int j2 = 0; j2 < 4; j2++) {
                phi[j2][0] = pack_h2(s[2*j2][0],   s[2*j2][1]);
                phi[j2][1] = pack_h2(s[2*j2][2],   s[2*j2][3]);
                phi[j2][2] = pack_h2(s[2*j2+1][0], s[2*j2+1][1]);
                phi[j2][3] = pack_h2(s[2*j2+1][2], s[2*j2+1][3]);
            }

            #pragma unroll
            for (int j2 = 0; j2 < 4; j2++) {
                int vrow = j2 * 16 + vrow_off;
                #pragma unroll
                for (int g = 0; g < 4; g++) {
                    int cg = g * 2 + vcg;
                    uint32_t off = (uint32_t)(vrow * 128 + ((cg ^ (vrow & 7)) * 16));
                    uint32_t vh[4];
                    ldsm4t(vh, st + 8192 + off);
                    mma_f16(acc_o[2*g],     phi[j2], &vh[0]);
                    mma_f16(acc_o[2*g + 1], phi[j2], &vh[2]);
                }
            }
        }
    }

    const int b = bh >> 4, h = bh & 15;
    const float inv0 = 1.f / l0, inv1 = 1.f / l1;
    #pragma unroll
    for (int nt = 0; nt < 8; nt++) {
        int d = nt * 8 + 2 * (lane & 3);
        size_t o0 = ((size_t)(b * TSEQ + r0g)) * DM + h * HD + d;
        size_t o1 = ((size_t)(b * TSEQ + r1g)) * DM + h * HD + d;
        *(uint32_t*)&oh_g[o0] = pack_h2(acc_o[nt][0] * inv0, acc_o[nt][1] * inv0);
        *(uint32_t*)&oh_g[o1] = pack_h2(acc_o[nt][2] * inv1, acc_o[nt][3] * inv1);
    }
}

// ---------------------------------------------------------------------------
extern "C" void kernel_launch(void* const* d_in, const int* in_sizes, int n_in,
                              void* d_out, int out_size)
{
    (void)in_sizes; (void)n_in; (void)out_size;
    const float* x     = (const float*)d_in[0];
    const float* qkv_w = (const float*)d_in[1];
    const float* qkv_b = (const float*)d_in[2];
    const float* out_w = (const float*)d_in[3];
    const float* out_b = (const float*)d_in[4];
    float* out = (float*)d_out;

    __half *xh, *w1h, *w2h, *ah, *qh, *kh, *vh;
    cudaGetSymbolAddress((void**)&xh,  g_xh);
    cudaGetSymbolAddress((void**)&w1h, g_w1h);
    cudaGetSymbolAddress((void**)&w2h, g_w2h);
    cudaGetSymbolAddress((void**)&ah,  g_ah);
    cudaGetSymbolAddress((void**)&qh,  g_qh);
    cudaGetSymbolAddress((void**)&kh,  g_kh);
    cudaGetSymbolAddress((void**)&vh,  g_vh);

    cudaFuncSetAttribute(mma_gemm<true>,  cudaFuncAttributeMaxDynamicSharedMemorySize, GEMM_SMEM);
    cudaFuncSetAttribute(mma_gemm<false>, cudaFuncAttributeMaxDynamicSharedMemorySize, GEMM_SMEM);
    cudaFuncSetAttribute(flash_mma, cudaFuncAttributeMaxDynamicSharedMemorySize, FL_SMEM);

    // 0) fp16 converts
    cvt3_kernel<<<(SPLIT_TOT + 255)/256, 256>>>(x, qkv_w, out_w);

    // 1) QKV projection (persistent, BK=64, 3-stage) -> fp16 q,k,v in [B,H,T,Hd]
    {
        int ntile = (MTOT/128) * (3*DM/128);
        int grid = ntile < 296 ? ntile : 296;
        mma_gemm<true><<<grid, 256, GEMM_SMEM>>>(xh, w1h, qkv_b, nullptr, 3*DM);
    }

    // 2) flash attention -> g_ah [B,T,D] (fp16)
    dim3 g2(TSEQ/128, BDIM*NH);
    flash_mma<<<g2, 256, FL_SMEM>>>(qh, kh, vh, ah);

    // 3) output projection (persistent, BK=64, 3-stage) -> d_out
    {
        int ntile = (MTOT/128) * (DM/128);
        int grid = ntile < 296 ? ntile : 296;
        mma_gemm<false><<<grid, 256, GEMM_SMEM>>>(ah, w2h, out_b, out, DM);
    }
}

// round 15
// speedup vs baseline: 1.0343x; 1.0343x over previous
#include <cuda_runtime.h>
#include <cuda_fp16.h>
#include <cstdint>

#define BDIM 2
#define TSEQ 2048
#define NH 16
#define HD 64
#define DM 1024
#define MTOT (BDIM*TSEQ)

// ---------------- scratch (allocation-free: __device__ globals) ----------------
__device__ uint4 g_xh[(size_t)MTOT*DM*2/16];
__device__ uint4 g_w1h[(size_t)3*DM*DM*2/16];
__device__ uint4 g_w2h[(size_t)DM*DM*2/16];
__device__ uint4 g_qh[(size_t)BDIM*NH*TSEQ*HD*2/16];
__device__ uint4 g_kh[(size_t)BDIM*NH*TSEQ*HD*2/16];
__device__ uint4 g_vh[(size_t)BDIM*NH*TSEQ*HD*2/16];
__device__ uint4 g_ah[(size_t)MTOT*DM*2/16];

// ---------------- helpers ----------------
__device__ __forceinline__ uint32_t smem_u32(const void* p) {
    uint32_t a;
    asm("{ .reg .u64 t; cvta.to.shared.u64 t, %1; cvt.u32.u64 %0, t; }" : "=r"(a) : "l"(p));
    return a;
}
__device__ __forceinline__ void cpasync16(uint32_t dst, const void* src) {
    asm volatile("cp.async.cg.shared.global [%0], [%1], 16;" :: "r"(dst), "l"(src) : "memory");
}
#define CP_COMMIT() asm volatile("cp.async.commit_group;" ::: "memory")
#define CP_WAIT1()  asm volatile("cp.async.wait_group 1;" ::: "memory")
#define CP_WAIT0()  asm volatile("cp.async.wait_group 0;" ::: "memory")
__device__ __forceinline__ void ldsm4(uint32_t* r, uint32_t addr) {
    asm volatile("ldmatrix.sync.aligned.m8n8.x4.shared.b16 {%0,%1,%2,%3}, [%4];"
        : "=r"(r[0]), "=r"(r[1]), "=r"(r[2]), "=r"(r[3]) : "r"(addr));
}
__device__ __forceinline__ void ldsm4t(uint32_t* r, uint32_t addr) {
    asm volatile("ldmatrix.sync.aligned.m8n8.x4.trans.shared.b16 {%0,%1,%2,%3}, [%4];"
        : "=r"(r[0]), "=r"(r[1]), "=r"(r[2]), "=r"(r[3]) : "r"(addr));
}
__device__ __forceinline__ void mma_f16(float* c, const uint32_t* a, const uint32_t* b) {
    asm volatile(
        "mma.sync.aligned.m16n8k16.row.col.f32.f16.f16.f32 "
        "{%0,%1,%2,%3}, {%4,%5,%6,%7}, {%8,%9}, {%0,%1,%2,%3};"
        : "+f"(c[0]), "+f"(c[1]), "+f"(c[2]), "+f"(c[3])
        : "r"(a[0]), "r"(a[1]), "r"(a[2]), "r"(a[3]), "r"(b[0]), "r"(b[1]));
}
__device__ __forceinline__ uint32_t pack_h2(float a, float b) {
    __half2 h = __floats2half2_rn(a, b);
    return reinterpret_cast<uint32_t&>(h);
}

// ---------------- fused fp32 -> fp16 convert over 3 tensors (8 floats/thread) ---
#define SPLIT_N0 (MTOT*DM/8)
#define SPLIT_N1 (3*DM*DM/8)
#define SPLIT_N2 (DM*DM/8)
#define SPLIT_TOT (SPLIT_N0 + SPLIT_N1 + SPLIT_N2)

__global__ __launch_bounds__(256)
void cvt3_kernel(const float* __restrict__ s0, const float* __restrict__ s1,
                 const float* __restrict__ s2)
{
    int i = blockIdx.x * blockDim.x + threadIdx.x;
    if (i >= SPLIT_TOT) return;
    const float* s; __half* hi; int j;
    if (i < SPLIT_N0)                  { s = s0; hi = (__half*)g_xh;  j = i; }
    else if (i < SPLIT_N0 + SPLIT_N1)  { s = s1; hi = (__half*)g_w1h; j = i - SPLIT_N0; }
    else                               { s = s2; hi = (__half*)g_w2h; j = i - SPLIT_N0 - SPLIT_N1; }
    float4 v0 = ((const float4*)s)[2*j];
    float4 v1 = ((const float4*)s)[2*j + 1];
    ((uint4*)hi)[j] = make_uint4(pack_h2(v0.x, v0.y), pack_h2(v0.z, v0.w),
                                 pack_h2(v1.x, v1.y), pack_h2(v1.z, v1.w));
}

// ---------------- persistent mma.sync GEMM, BK=64, 2-stage (R13 champion) -------
#define BK 64
#define NCH (DM / BK)               // 16
#define TILE_B 16384                // 128 rows x 128B
#define STAGE_B (2 * TILE_B)        // A, W: 32768
#define GEMM_SMEM (2 * STAGE_B)     // 65536

template<bool SCATTER>
__global__ __launch_bounds__(256, 2)
void mma_gemm(const __half* __restrict__ A, const __half* __restrict__ W,
              const float* __restrict__ bias, float* __restrict__ C, int N)
{
    extern __shared__ char smem[];
    const uint32_t sbase = smem_u32(smem);
    const int tid = threadIdx.x, wid = tid >> 5, lane = tid & 31;
    const int wm = wid & 3, wn = wid >> 2;
    const int K = DM;
    const int nx = N >> 7;
    const int ntile = (MTOT >> 7) * nx;

    auto load_stage = [&](int m0, int n0, int c, int stg) {
        const uint32_t st = sbase + (uint32_t)stg * STAGE_B;
        const int k0 = c * BK;
        #pragma unroll
        for (int t = 0; t < 4; t++) {
            int idx = tid + t * 256;            // 0..1023
            int row = idx >> 3, ch = idx & 7;
            uint32_t so = (uint32_t)(row * 128 + ((ch ^ (row & 7)) * 16));
            int gk = k0 + ch * 8;
            cpasync16(st + so,          A + (size_t)(m0 + row) * K + gk);
            cpasync16(st + TILE_B + so, W + (size_t)(n0 + row) * K + gk);
        }
        CP_COMMIT();
    };

    const int arowoff = lane & 15;
    const int akoff   = lane >> 4;
    const int browoff = (lane & 7) + ((lane >> 4) << 3);
    const int bkoff   = (lane >> 3) & 1;

    int rowA[2];
    #pragma unroll
    for (int mt = 0; mt < 2; mt++)
        rowA[mt] = wm * 32 + mt * 16 + arowoff;
    int rowB[4];
    #pragma unroll
    for (int nt2 = 0; nt2 < 4; nt2++)
        rowB[nt2] = wn * 64 + nt2 * 16 + browoff;

    {
        int t0 = blockIdx.x;
        if (t0 < ntile) load_stage((t0 / nx) << 7, (t0 % nx) << 7, 0, 0);
    }

    for (int tile = blockIdx.x; tile < ntile; tile += gridDim.x) {
        const int m0 = (tile / nx) << 7, n0 = (tile % nx) << 7;
        const int tnext = tile + gridDim.x;
        const bool has_next = tnext < ntile;
        const int mn = has_next ? ((tnext / nx) << 7) : 0;
        const int nn = has_next ? ((tnext % nx) << 7) : 0;

        float acc[2][8][4];
        #pragma unroll
        for (int mt = 0; mt < 2; mt++)
            #pragma unroll
            for (int nt = 0; nt < 8; nt++)
                #pragma unroll
                for (int q = 0; q < 4; q++) acc[mt][nt][q] = 0.f;

        for (int c = 0; c < NCH; c++) {
            const int cur = c & 1;
            if (c + 1 < NCH) {
                load_stage(m0, n0, c + 1, cur ^ 1);
                CP_WAIT1();
            } else if (has_next) {
                load_stage(mn, nn, 0, 0);   // (NCH-1)&1 ^ 1 == 0 (NCH even)
                CP_WAIT1();
            } else {
                CP_WAIT0();
            }
            __syncthreads();

            const uint32_t st = sbase + (uint32_t)cur * STAGE_B;
            #pragma unroll
            for (int s = 0; s < 4; s++) {
                uint32_t ah[2][4];
                #pragma unroll
                for (int mt = 0; mt < 2; mt++) {
                    uint32_t off = (uint32_t)(rowA[mt] * 128 + (((2*s + akoff) ^ (rowA[mt] & 7)) * 16));
                    ldsm4(ah[mt], st + off);
                }
                uint32_t bh[4][4];
                #pragma unroll
                for (int nt2 = 0; nt2 < 4; nt2++) {
                    uint32_t off = (uint32_t)(rowB[nt2] * 128 + (((2*s + bkoff) ^ (rowB[nt2] & 7)) * 16));
                    ldsm4(bh[nt2], st + TILE_B + off);
                }
                #pragma unroll
                for (int mt = 0; mt < 2; mt++)
                    #pragma unroll
                    for (int nt = 0; nt < 8; nt++)
                        mma_f16(acc[mt][nt], ah[mt], &bh[nt >> 1][(nt & 1) * 2]);
            }
            __syncthreads();
        }

        const int lr = lane >> 2, lc = (lane & 3) * 2;
        #pragma unroll
        for (int mt = 0; mt < 2; mt++) {
            #pragma unroll
            for (int half = 0; half < 2; half++) {
                const int m = m0 + wm * 32 + mt * 16 + lr + half * 8;
                #pragma unroll
                for (int nt = 0; nt < 8; nt++) {
                    const int n = n0 + wn * 64 + nt * 8 + lc;
                    float rx = acc[mt][nt][half * 2 + 0] + bias[n + 0];
                    float ry = acc[mt][nt][half * 2 + 1] + bias[n + 1];
                    if (!SCATTER) {
                        *(float2*)&C[(size_t)m * N + n] = make_float2(rx, ry);
                    } else {
                        int mat = n >> 10, h = (n >> 6) & 15, d = n & 63;
                        int b = m >> 11, t = m & 2047;
                        // q pre-scaled by 0.125 * log2(e) so flash can use exp2
                        if (mat == 0) { rx *= 0.18033688f; ry *= 0.18033688f; }
                        __half* dh = (mat == 0) ? (__half*)g_qh
                                    : (mat == 1) ? (__half*)g_kh : (__half*)g_vh;
                        size_t off = (((size_t)(b * NH + h) * TSEQ) + t) * HD + d;
                        *(uint32_t*)&dh[off] = pack_h2(rx, ry);
                    }
                }
            }
        }
    }
}

// ---------------- flash attention (R13 config: exp2, per-warp skip) -------------
#define FL_Q 0u
#define FL_STG 16384u
#define FL_SSZ 16384u              // K 8KB + V 8KB
#define FL_SMEM (FL_STG + 2 * FL_SSZ)   // 49152

__global__ __launch_bounds__(256, 2)
void flash_mma(const __half* __restrict__ qh_g,
               const __half* __restrict__ kh_g, const __half* __restrict__ vh_g,
               __half* __restrict__ oh_g)
{
    extern __shared__ char smem[];
    const uint32_t sb = smem_u32(smem);
    const int tid = threadIdx.x, wid = tid >> 5, lane = tid & 31;
    const int bh = blockIdx.y;
    const int qb = gridDim.x - 1 - blockIdx.x;     // heavy tiles first
    const int qbase = qb * 128;
    const size_t base = (size_t)bh * TSEQ * HD;
    const int nkb = 2 * qb + 2;

    auto ldq = [&]() {
        #pragma unroll
        for (int t = 0; t < 4; t++) {
            int idx = tid + t * 256;
            int row = idx >> 3, ch = idx & 7;
            uint32_t so = (uint32_t)(row * 128 + ((ch ^ (row & 7)) * 16));
            cpasync16(sb + FL_Q + so, qh_g + base + (size_t)(qbase + row) * HD + ch * 8);
        }
    };
    auto ldkv = [&](int kb, int stg) {
        const uint32_t st = sb + FL_STG + (uint32_t)stg * FL_SSZ;
        #pragma unroll
        for (int t = 0; t < 2; t++) {
            int idx = tid + t * 256;
            int row = idx >> 3, ch = idx & 7;
            uint32_t so = (uint32_t)(row * 128 + ((ch ^ (row & 7)) * 16));
            size_t g = base + (size_t)(kb * 64 + row) * HD + ch * 8;
            cpasync16(st + so,        kh_g + g);
            cpasync16(st + 8192 + so, vh_g + g);
        }
        CP_COMMIT();
    };

    ldq();
    ldkv(0, 0);

    const int arow = wid * 16 + (lane & 15);
    const int akoff = lane >> 4;
    const int brow_off = (lane & 7) + ((lane >> 4) << 3);
    const int bkoff = (lane >> 3) & 1;
    const int vrow_off = (lane & 7) + (((lane >> 3) & 1) << 3);
    const int vcg = lane >> 4;

    const int wrow0 = qbase + wid * 16;
    const int wrow_max = wrow0 + 15;

    uint32_t qh[4][4];
    float acc_o[8][4];
    #pragma unroll
    for (int nt = 0; nt < 8; nt++)
        #pragma unroll
        for (int q = 0; q < 4; q++) acc_o[nt][q] = 0.f;
    float m0 = -1e30f, m1 = -1e30f, l0 = 0.f, l1 = 0.f;

    const int r0g = wrow0 + (lane >> 2);
    const int r1g = r0g + 8;

    for (int kb = 0; kb < nkb; kb++) {
        const int cur = kb & 1;
        if (kb + 1 < nkb) {
            ldkv(kb + 1, cur ^ 1);
            CP_WAIT1();
        } else {
            CP_WAIT0();
        }
        __syncthreads();

        if (kb == 0) {
            #pragma unroll
            for (int s4 = 0; s4 < 4; s4++) {
                uint32_t off = (uint32_t)(arow * 128 + (((2*s4 + akoff) ^ (arow & 7)) * 16));
                ldsm4(qh[s4], sb + FL_Q + off);
            }
        }

        const int kbase = kb * 64;
        if (kbase <= wrow_max) {   // skip fully-masked tiles (bit-identical)
            const uint32_t st = sb + FL_STG + (uint32_t)cur * FL_SSZ;

            float s[8][4];
            #pragma unroll
            for (int nt = 0; nt < 8; nt++)
                #pragma unroll
                for (int q = 0; q < 4; q++) s[nt][q] = 0.f;

            #pragma unroll
            for (int s4 = 0; s4 < 4; s4++) {
                uint32_t kh[4][4];
                #pragma unroll
                for (int nt2 = 0; nt2 < 4; nt2++) {
                    int row = nt2 * 16 + brow_off;
                    uint32_t off = (uint32_t)(row * 128 + (((2*s4 + bkoff) ^ (row & 7)) * 16));
                    ldsm4(kh[nt2], st + off);
                }
                #pragma unroll
                for (int nt = 0; nt < 8; nt++)
                    mma_f16(s[nt], qh[s4], &kh[nt >> 1][(nt & 1) * 2]);
            }

            if (kbase + 63 > wrow0) {
                #pragma unroll
                for (int nt = 0; nt < 8; nt++) {
                    int kg0 = kbase + nt * 8 + 2 * (lane & 3);
                    if (kg0 > r0g)     s[nt][0] = -1e30f;
                    if (kg0 + 1 > r0g) s[nt][1] = -1e30f;
                    if (kg0 > r1g)     s[nt][2] = -1e30f;
                    if (kg0 + 1 > r1g) s[nt][3] = -1e30f;
                }
            }

            float mx0 = -1e30f, mx1 = -1e30f;
            #pragma unroll
            for (int nt = 0; nt < 8; nt++) {
                mx0 = fmaxf(mx0, fmaxf(s[nt][0], s[nt][1]));
                mx1 = fmaxf(mx1, fmaxf(s[nt][2], s[nt][3]));
            }
            mx0 = fmaxf(mx0, __shfl_xor_sync(0xffffffffu, mx0, 1));
            mx0 = fmaxf(mx0, __shfl_xor_sync(0xffffffffu, mx0, 2));
            mx1 = fmaxf(mx1, __shfl_xor_sync(0xffffffffu, mx1, 1));
            mx1 = fmaxf(mx1, __shfl_xor_sync(0xffffffffu, mx1, 2));
            float mn0 = fmaxf(m0, mx0), mn1 = fmaxf(m1, mx1);
            // scores are in log2 units (q pre-scaled by 0.125*log2e) -> exp2
            float a0 = exp2f(m0 - mn0), a1 = exp2f(m1 - mn1);
            float sum0 = 0.f, sum1 = 0.f;
            #pragma unroll
            for (int nt = 0; nt < 8; nt++) {
                s[nt][0] = exp2f(s[nt][0] - mn0);
                s[nt][1] = exp2f(s[nt][1] - mn0);
                s[nt][2] = exp2f(s[nt][2] - mn1);
                s[nt][3] = exp2f(s[nt][3] - mn1);
                sum0 += s[nt][0] + s[nt][1];
                sum1 += s[nt][2] + s[nt][3];
            }
            sum0 += __shfl_xor_sync(0xffffffffu, sum0, 1);
            sum0 += __shfl_xor_sync(0xffffffffu, sum0, 2);
            sum1 += __shfl_xor_sync(0xffffffffu, sum1, 1);
            sum1 += __shfl_xor_sync(0xffffffffu, sum1, 2);
            l0 = l0 * a0 + sum0; m0 = mn0;
            l1 = l1 * a1 + sum1; m1 = mn1;
            #pragma unroll
            for (int nt = 0; nt < 8; nt++) {
                acc_o[nt][0] *= a0; acc_o[nt][1] *= a0;
                acc_o[nt][2] *= a1; acc_o[nt][3] *= a1;
            }

            uint32_t phi[4][4];
            #pragma unroll
            for (int j2 = 0; j2 < 4; j2++) {
                phi[j2][0] = pack_h2(s[2*j2][0],   s[2*j2][1]);
                phi[j2][1] = pack_h2(s[2*j2][2],   s[2*j2][3]);
                phi[j2][2] = pack_h2(s[2*j2+1][0], s[2*j2+1][1]);
                phi[j2][3] = pack_h2(s[2*j2+1][2], s[2*j2+1][3]);
            }

            #pragma unroll
            for (int j2 = 0; j2 < 4; j2++) {
                int vrow = j2 * 16 + vrow_off;
                #pragma unroll
                for (int g = 0; g < 4; g++) {
                    int cg = g * 2 + vcg;
                    uint32_t off = (uint32_t)(vrow * 128 + ((cg ^ (vrow & 7)) * 16));
                    uint32_t vh[4];
                    ldsm4t(vh, st + 8192 + off);
                    mma_f16(acc_o[2*g],     phi[j2], &vh[0]);
                    mma_f16(acc_o[2*g + 1], phi[j2], &vh[2]);
                }
            }
        }
        __syncthreads();
    }

    const int b = bh >> 4, h = bh & 15;
    const float inv0 = 1.f / l0, inv1 = 1.f / l1;
    #pragma unroll
    for (int nt = 0; nt < 8; nt++) {
        int d = nt * 8 + 2 * (lane & 3);
        size_t o0 = ((size_t)(b * TSEQ + r0g)) * DM + h * HD + d;
        size_t o1 = ((size_t)(b * TSEQ + r1g)) * DM + h * HD + d;
        *(uint32_t*)&oh_g[o0] = pack_h2(acc_o[nt][0] * inv0, acc_o[nt][1] * inv0);
        *(uint32_t*)&oh_g[o1] = pack_h2(acc_o[nt][2] * inv1, acc_o[nt][3] * inv1);
    }
}

// ---------------------------------------------------------------------------
extern "C" void kernel_launch(void* const* d_in, const int* in_sizes, int n_in,
                              void* d_out, int out_size)
{
    (void)in_sizes; (void)n_in; (void)out_size;
    const float* x     = (const float*)d_in[0];
    const float* qkv_w = (const float*)d_in[1];
    const float* qkv_b = (const float*)d_in[2];
    const float* out_w = (const float*)d_in[3];
    const float* out_b = (const float*)d_in[4];
    float* out = (float*)d_out;

    __half *xh, *w1h, *w2h, *ah, *qh, *kh, *vh;
    cudaGetSymbolAddress((void**)&xh,  g_xh);
    cudaGetSymbolAddress((void**)&w1h, g_w1h);
    cudaGetSymbolAddress((void**)&w2h, g_w2h);
    cudaGetSymbolAddress((void**)&ah,  g_ah);
    cudaGetSymbolAddress((void**)&qh,  g_qh);
    cudaGetSymbolAddress((void**)&kh,  g_kh);
    cudaGetSymbolAddress((void**)&vh,  g_vh);

    cudaFuncSetAttribute(mma_gemm<true>,  cudaFuncAttributeMaxDynamicSharedMemorySize, GEMM_SMEM);
    cudaFuncSetAttribute(mma_gemm<false>, cudaFuncAttributeMaxDynamicSharedMemorySize, GEMM_SMEM);
    cudaFuncSetAttribute(flash_mma, cudaFuncAttributeMaxDynamicSharedMemorySize, FL_SMEM);

    // 0) fp16 converts (8 floats/thread)
    cvt3_kernel<<<(SPLIT_TOT + 255)/256, 256>>>(x, qkv_w, out_w);

    // 1) QKV projection (persistent, BK=64) -> fp16 q,k,v in [B,H,T,Hd]
    //    768 tiles on grid 288: ceil = 3 (same critical path as 296, fully packed)
    mma_gemm<true><<<288, 256, GEMM_SMEM>>>(xh, w1h, qkv_b, nullptr, 3*DM);

    // 2) flash attention -> g_ah [B,T,D] (fp16)
    dim3 g2(TSEQ/128, BDIM*NH);
    flash_mma<<<g2, 256, FL_SMEM>>>(qh, kh, vh, ah);

    // 3) output projection (persistent, BK=64) -> d_out (256 tiles, grid 256)
    mma_gemm<false><<<256, 256, GEMM_SMEM>>>(ah, w2h, out_b, out, DM);
}